// round 12
// baseline (speedup 1.0000x reference)
#include <cuda_runtime.h>
#include <cuda_fp16.h>
#include <cstdint>
#include <cmath>

constexpr int BATCH = 8;
constexpr int SEQ   = 4096;
constexpr int DIM   = 768;
constexpr int NST   = 16;
constexpr int ROWS  = BATCH * SEQ;        // 32768
constexpr int CHUNK = 32;
constexpr int NCHUNK = SEQ / CHUNK;       // 128
constexpr int NTASK  = BATCH * NCHUNK;    // 1024

__device__ float  d_gu[ROWS * NST];
__device__ float  d_lend[NTASK * NST];
__device__ float  d_hstart[NTASK * NST];
__device__ float  d_Ppow[CHUNK * NST * NST];   // Ppow[j] = T^(j+1)
__device__ float  d_Qsq[7 * NST * NST];        // Qsq[t] = (T^C)^(2^t)
__device__ __half d_xh[ROWS * DIM];            // fp16 x (written by gemm1)
__device__ __half d_wsk[DIM * DIM];            // fp16 W_skip
__device__ __half d_hsh[ROWS * NST];           // fp16 hs (written by fixup)
__device__ __half d_woh[DIM * NST];            // fp16 W_out

#define DEVI __device__ __forceinline__

DEVI uint32_t smem_u32(const void* p) {
    uint32_t a;
    asm("{ .reg .u64 t; cvta.to.shared.u64 t, %1; cvt.u32.u64 %0, t; }" : "=r"(a) : "l"(p));
    return a;
}
DEVI void cpa16(uint32_t dst, const void* src) {
    asm volatile("cp.async.ca.shared.global [%0], [%1], 16;" :: "r"(dst), "l"(src));
}
DEVI void cpa_commit() { asm volatile("cp.async.commit_group;"); }
DEVI void cpa_wait2()  { asm volatile("cp.async.wait_group 2;"); }
DEVI void ldm4(uint32_t* r, uint32_t a) {
    asm volatile("ldmatrix.sync.aligned.m8n8.x4.shared.b16 {%0,%1,%2,%3}, [%4];"
                 : "=r"(r[0]), "=r"(r[1]), "=r"(r[2]), "=r"(r[3]) : "r"(a));
}
DEVI void mma16816(float* c, const uint32_t* a, uint32_t b0, uint32_t b1) {
    asm volatile(
        "mma.sync.aligned.m16n8k16.row.col.f32.f16.f16.f32 "
        "{%0,%1,%2,%3},{%4,%5,%6,%7},{%8,%9},{%0,%1,%2,%3};"
        : "+f"(c[0]), "+f"(c[1]), "+f"(c[2]), "+f"(c[3])
        : "r"(a[0]), "r"(a[1]), "r"(a[2]), "r"(a[3]), "r"(b0), "r"(b1));
}
DEVI float dot4(float4 a, float4 b) {
    return a.x * b.x + a.y * b.y + a.z * b.z + a.w * b.w;
}

// --------------------------------------------------------------------------
// per-chunk local scan (h0=0), in place, one-deep prefetch
// --------------------------------------------------------------------------
__global__ void __launch_bounds__(64) k_scan_local() {
    int tid = threadIdx.x;
    int task = blockIdx.x * 4 + (tid >> 4);
    int n = tid & 15;
    float Trow[16];
#pragma unroll
    for (int m = 0; m < 16; m++) Trow[m] = d_Ppow[n * 16 + m];
    float* g = d_gu + (size_t)task * CHUNK * NST;
    float h = 0.f;
    float nxt = g[n];
    for (int j = 0; j < CHUNK; j++) {
        float curv = nxt;
        if (j + 1 < CHUNK) nxt = g[(j + 1) * NST + n];
        float hn = curv;
#pragma unroll
        for (int m = 0; m < 16; m++)
            hn += Trow[m] * __shfl_sync(0xffffffffu, h, m, 16);
        h = hn;
        g[j * NST + n] = h;
    }
    d_lend[task * NST + n] = h;
}

// --------------------------------------------------------------------------
// mid scan: Kogge-Stone over 128 chunk states per batch; float4-vectorized.
// --------------------------------------------------------------------------
__global__ void __launch_bounds__(512) k_scan_mid() {
    __shared__ float4 buf0[512], buf1[512];
    __shared__ float  Qs[7 * 256];
    int b = blockIdx.x, tid = threadIdx.x;
    for (int i = tid; i < 7 * 256; i += 512) Qs[i] = d_Qsq[i];
    buf0[tid] = ((const float4*)(d_lend + b * 2048))[tid];
    __syncthreads();
    float4* src = buf0;
    float4* dst = buf1;
    int k = tid >> 2, q = tid & 3;
#pragma unroll
    for (int t = 0; t < 7; t++) {
        int o = 1 << t;
        const float4* Q4 = (const float4*)(Qs + t * 256);
        float4 v = src[tid];
        if (k >= o) {
            const float4* sp = src + ((k - o) << 2);
            float4 s0 = sp[0], s1 = sp[1], s2 = sp[2], s3 = sp[3];
            float acc[4];
#pragma unroll
            for (int e = 0; e < 4; e++) {
                int n = q * 4 + e;
                acc[e] = dot4(Q4[n * 4], s0) + dot4(Q4[n * 4 + 1], s1)
                       + dot4(Q4[n * 4 + 2], s2) + dot4(Q4[n * 4 + 3], s3);
            }
            v.x += acc[0]; v.y += acc[1]; v.z += acc[2]; v.w += acc[3];
        }
        dst[tid] = v;
        __syncthreads();
        float4* tmp = src; src = dst; dst = tmp;
    }
    float4 out = (k == 0) ? make_float4(0.f, 0.f, 0.f, 0.f) : src[((k - 1) << 2) + q];
    ((float4*)(d_hstart + (size_t)b * NCHUNK * NST))[tid] = out;
}

// --------------------------------------------------------------------------
// fix-up h_t = local_t + T^(j+1) s_k -> fp16 hs ; float4-vectorized
// --------------------------------------------------------------------------
__global__ void __launch_bounds__(256) k_fixup() {
    int gid = blockIdx.x * 256 + threadIdx.x;
    int r = gid >> 2, q = gid & 3;
    int b = r >> 12, t = r & 4095;
    int k = t >> 5, j = t & 31;
    const float4* P4 = (const float4*)(d_Ppow + j * 256);
    const float4* s4 = (const float4*)(d_hstart + (size_t)(b * NCHUNK + k) * NST);
    float4 s0 = s4[0], s1 = s4[1], s2 = s4[2], s3 = s4[3];
    float4 g = ((const float4*)d_gu)[gid];
    float acc[4] = {g.x, g.y, g.z, g.w};
#pragma unroll
    for (int e = 0; e < 4; e++) {
        int n = q * 4 + e;
        acc[e] += dot4(P4[n * 4], s0) + dot4(P4[n * 4 + 1], s1)
                + dot4(P4[n * 4 + 2], s2) + dot4(P4[n * 4 + 3], s3);
    }
    __half2 h0 = __floats2half2_rn(acc[0], acc[1]);
    __half2 h1 = __floats2half2_rn(acc[2], acc[3]);
    uint2 pk = make_uint2(*(uint32_t*)&h0, *(uint32_t*)&h1);
    ((uint2*)d_hsh)[gid] = pk;
}

// --------------------------------------------------------------------------
// GEMM1 (+ fused prep): blocks 0..255 compute gu tile; blocks 256.. do prep.
// --------------------------------------------------------------------------
constexpr int G1_BS = 776;
constexpr int G1_B  = 0;                       // 32*776*2 = 49664
constexpr int G1_A  = 49664;                   // 4 * 128*40*2 = 40960
constexpr int G1_BIAS = G1_A + 40960;          // 90624
constexpr int G1TOTAL = G1_BIAS + 128;
constexpr int AST = 40;
constexpr int G1_GEMM_BLKS = 256;
constexpr int G1_PREP_BLKS = 589;              // 1 powers + 576 Wskip + 12 Wout

__global__ void __launch_bounds__(256, 2) k_gemm1(const float* __restrict__ x,
                                                  const float* __restrict__ Win,
                                                  const float* __restrict__ Wgate,
                                                  const float* __restrict__ bin,
                                                  const float* __restrict__ bgate,
                                                  const float* __restrict__ a_logit,
                                                  const float* __restrict__ U,
                                                  const float* __restrict__ V,
                                                  const float* __restrict__ Wskip,
                                                  const float* __restrict__ Wout) {
    int tid = threadIdx.x;
    if (blockIdx.x >= G1_GEMM_BLKS) {
        int pbid = blockIdx.x - G1_GEMM_BLKS;
        if (pbid == 0) {
            __shared__ float Ts[256], cur[256];
            int n = tid >> 4, m = tid & 15;
            float acc = 0.f;
#pragma unroll
            for (int r = 0; r < 8; r++) acc += V[m * 8 + r] * U[n * 8 + r];
            if (m == n) acc += 1.f / (1.f + expf(-a_logit[n]));
            Ts[tid] = acc; cur[tid] = acc; d_Ppow[tid] = acc;
            __syncthreads();
            for (int j = 1; j < CHUNK; j++) {
                float s = 0.f;
#pragma unroll
                for (int q = 0; q < 16; q++) s += Ts[n * 16 + q] * cur[q * 16 + m];
                __syncthreads();
                cur[tid] = s; d_Ppow[j * 256 + tid] = s;
                __syncthreads();
            }
            for (int tt = 0; tt < 7; tt++) {
                d_Qsq[tt * 256 + tid] = cur[tid];
                float s = 0.f;
#pragma unroll
                for (int q = 0; q < 16; q++) s += cur[n * 16 + q] * cur[q * 16 + m];
                __syncthreads();
                cur[tid] = s;
                __syncthreads();
            }
        } else if (pbid <= 576) {
            int i = (pbid - 1) * 256 + tid;        // float4 index into Wskip
            float4 v = ((const float4*)Wskip)[i];
            ((__half2*)d_wsk)[2 * i]     = __floats2half2_rn(v.x, v.y);
            ((__half2*)d_wsk)[2 * i + 1] = __floats2half2_rn(v.z, v.w);
        } else {
            int j = (pbid - 577) * 256 + tid;      // float4 index into Wout
            if (j < DIM * NST / 4) {
                float4 v = ((const float4*)Wout)[j];
                ((__half2*)d_woh)[2 * j]     = __floats2half2_rn(v.x, v.y);
                ((__half2*)d_woh)[2 * j + 1] = __floats2half2_rn(v.z, v.w);
            }
        }
        return;
    }

    extern __shared__ char smem[];
    __half* sBh = (__half*)(smem + G1_B);
    __half* sAh = (__half*)(smem + G1_A);
    float*  sb  = (float*)(smem + G1_BIAS);
    int w = tid >> 5, l = tid & 31;
    int mt = blockIdx.x;

    for (int i = tid; i < 6144; i += 256) {
        int row = i / 192, c4 = i % 192;
        const float* src = (row < 16) ? (Win + (size_t)row * DIM) : (Wgate + (size_t)(row - 16) * DIM);
        float4 v = ((const float4*)src)[c4];
        *(__half2*)(sBh + row * G1_BS + c4 * 4)     = __floats2half2_rn(v.x, v.y);
        *(__half2*)(sBh + row * G1_BS + c4 * 4 + 2) = __floats2half2_rn(v.z, v.w);
    }
    if (tid < 16) { sb[tid] = bin[tid]; sb[16 + tid] = bgate[tid]; }

    int arow = tid >> 1, ahalf = tid & 1;
    const float* Abase = x + (size_t)(mt * 128 + arow) * DIM + ahalf * 16;
    __half* xdst = d_xh + (size_t)(mt * 128 + arow) * DIM + ahalf * 16;

    auto convert_store = [&](const float4* rg, int kc) {
        uint32_t hp[8];
#pragma unroll
        for (int q = 0; q < 4; q++) {
            __half2 h0 = __floats2half2_rn(rg[q].x, rg[q].y);
            __half2 h1 = __floats2half2_rn(rg[q].z, rg[q].w);
            hp[2 * q]     = *(uint32_t*)&h0;
            hp[2 * q + 1] = *(uint32_t*)&h1;
        }
        __half* Ad = sAh + (kc & 3) * (128 * AST) + arow * AST + ahalf * 16;
        *(uint4*)Ad       = make_uint4(hp[0], hp[1], hp[2], hp[3]);
        *(uint4*)(Ad + 8) = make_uint4(hp[4], hp[5], hp[6], hp[7]);
        *(uint4*)(xdst + kc * 32)     = make_uint4(hp[0], hp[1], hp[2], hp[3]);
        *(uint4*)(xdst + kc * 32 + 8) = make_uint4(hp[4], hp[5], hp[6], hp[7]);
    };

    float4 rg[4];
#pragma unroll
    for (int q = 0; q < 4; q++) rg[q] = ((const float4*)Abase)[q];
    convert_store(rg, 0);
#pragma unroll
    for (int q = 0; q < 4; q++) rg[q] = ((const float4*)(Abase + 32))[q];

    float c[4][4];
#pragma unroll
    for (int i = 0; i < 4; i++)
#pragma unroll
        for (int j = 0; j < 4; j++) c[i][j] = 0.f;

    uint32_t aAddr = smem_u32(sAh);
    uint32_t bAddr = smem_u32(sBh);

    for (int kc = 0; kc < 24; kc++) {
        __syncthreads();
        if (kc < 23) {
            convert_store(rg, kc + 1);
            if (kc < 22) {
                const float4* nsrc = (const float4*)(Abase + (kc + 2) * 32);
#pragma unroll
                for (int q = 0; q < 4; q++) rg[q] = nsrc[q];
            }
        }
        uint32_t Ab = aAddr + (kc & 3) * (128 * AST * 2);
        uint32_t Bb = bAddr + kc * 32 * 2;
#pragma unroll
        for (int ks = 0; ks < 2; ks++) {
            uint32_t a[4];
            ldm4(a, Ab + ((w * 16 + (l & 15)) * AST + ks * 16 + (l >> 4) * 8) * 2);
            uint32_t bf[2][4];
#pragma unroll
            for (int i = 0; i < 2; i++)
                ldm4(bf[i], Bb + ((i * 16 + (l & 15)) * G1_BS + ks * 16 + (l >> 4) * 8) * 2);
#pragma unroll
            for (int nt = 0; nt < 4; nt++)
                mma16816(c[nt], a, bf[nt >> 1][nt & 1], bf[nt >> 1][(nt & 1) + 2]);
        }
    }

    int g = l >> 2, t2 = (l & 3) * 2;
#pragma unroll
    for (int h = 0; h < 2; h++) {
        int r = mt * 128 + w * 16 + h * 8 + g;
#pragma unroll
        for (int nt = 0; nt < 2; nt++) {
            float v[2];
#pragma unroll
            for (int e = 0; e < 2; e++) {
                int col = nt * 8 + t2 + e;
                float u  = c[nt][2 * h + e] + sb[col];
                float gp = c[nt + 2][2 * h + e] + sb[16 + col];
                v[e] = u / (1.f + expf(-gp));
            }
            *(float2*)(d_gu + (size_t)r * 16 + nt * 8 + t2) = make_float2(v[0], v[1]);
        }
    }
}

// --------------------------------------------------------------------------
// GEMM2: y = [x | hs] [Wskip | Wout]^T + b_out + b_skip
// CTA tile 256x128 (grid 6 x 128), 8 warps 4m x 2n, warp tile 64x64.
// 4-stage cp.async, 1 CTA/SM (123 KB smem, ~185 regs).
// --------------------------------------------------------------------------
constexpr int G2_AS  = 20480;                 // A bytes/stage (256*40*2)
constexpr int G2_STG = 30720;                 // stage stride (A + B)
constexpr int G2_BI  = 4 * G2_STG;            // 122880
constexpr int G2TOTAL = G2_BI + 512;          // 123392
constexpr int NKT = 25;

__global__ void __launch_bounds__(256, 1) k_gemm2(const float* __restrict__ bout,
                                                  const float* __restrict__ bskip,
                                                  float* __restrict__ y) {
    extern __shared__ char smem[];
    uint32_t sb = smem_u32(smem);
    int tid = threadIdx.x, w = tid >> 5, l = tid & 31;
    int nt = blockIdx.x, mt = blockIdx.y;
    int mw = w >> 1, nw = w & 1;

    float* sBias = (float*)(smem + G2_BI);
    if (tid < 128) sBias[tid] = bout[nt * 128 + tid] + bskip[nt * 128 + tid];

    const __half* Asrc = d_xh + (size_t)mt * 256 * DIM;
    const __half* Bsrc = d_wsk + (size_t)nt * 128 * DIM;
    const __half* Ahs  = d_hsh + (size_t)mt * 256 * NST;
    const __half* Bwo  = d_woh + (size_t)nt * 128 * NST;

    auto load_stage = [&](int kc) {
        uint32_t Ad = sb + (kc & 3) * G2_STG;
        uint32_t Bd = Ad + G2_AS;
        if (kc < 24) {
#pragma unroll
            for (int q = 0; q < 4; q++) {          // A: 1024 segs (256 rows x 4)
                int s = tid + q * 256;
                int row = s >> 2, cs = s & 3;
                cpa16(Ad + (row * AST + cs * 8) * 2, Asrc + (size_t)row * DIM + kc * 32 + cs * 8);
            }
#pragma unroll
            for (int q = 0; q < 2; q++) {          // B: 512 segs (128 rows x 4)
                int s = tid + q * 256;
                int row = s >> 2, cs = s & 3;
                cpa16(Bd + (row * AST + cs * 8) * 2, Bsrc + (size_t)row * DIM + kc * 32 + cs * 8);
            }
        } else {
            char* Ah = smem + (kc & 3) * G2_STG;
            char* Bh = Ah + G2_AS;
#pragma unroll
            for (int q = 0; q < 4; q++) {
                int s = tid + q * 256;
                int row = s >> 2, cs = s & 3;
                if (cs < 2) cpa16(Ad + (row * AST + cs * 8) * 2, Ahs + row * NST + cs * 8);
                else *(uint4*)(Ah + (row * AST + cs * 8) * 2) = make_uint4(0u, 0u, 0u, 0u);
            }
#pragma unroll
            for (int q = 0; q < 2; q++) {
                int s = tid + q * 256;
                int row = s >> 2, cs = s & 3;
                if (cs < 2) cpa16(Bd + (row * AST + cs * 8) * 2, Bwo + row * NST + cs * 8);
                else *(uint4*)(Bh + (row * AST + cs * 8) * 2) = make_uint4(0u, 0u, 0u, 0u);
            }
        }
    };

    float c[4][8][4];
#pragma unroll
    for (int i = 0; i < 4; i++)
#pragma unroll
        for (int j = 0; j < 8; j++)
#pragma unroll
            for (int e = 0; e < 4; e++) c[i][j][e] = 0.f;

    load_stage(0); cpa_commit();
    load_stage(1); cpa_commit();

    for (int kc = 0; kc < NKT; kc++) {
        if (kc + 2 < NKT) load_stage(kc + 2);
        cpa_commit();
        cpa_wait2();
        __syncthreads();
        uint32_t Ab = sb + (kc & 3) * G2_STG;
        uint32_t Bb = Ab + G2_AS;
#pragma unroll
        for (int ks = 0; ks < 2; ks++) {
            uint32_t a[4][4];
#pragma unroll
            for (int m4 = 0; m4 < 4; m4++)
                ldm4(a[m4], Ab + ((mw * 64 + m4 * 16 + (l & 15)) * AST + ks * 16 + (l >> 4) * 8) * 2);
            uint32_t bf[4][4];
#pragma unroll
            for (int i = 0; i < 4; i++)
                ldm4(bf[i], Bb + ((nw * 64 + i * 16 + (l & 15)) * AST + ks * 16 + (l >> 4) * 8) * 2);
#pragma unroll
            for (int m4 = 0; m4 < 4; m4++)
#pragma unroll
                for (int n2 = 0; n2 < 8; n2++)
                    mma16816(c[m4][n2], a[m4], bf[n2 >> 1][n2 & 1], bf[n2 >> 1][(n2 & 1) + 2]);
        }
    }

    int g = l >> 2, t2 = (l & 3) * 2;
#pragma unroll
    for (int m4 = 0; m4 < 4; m4++) {
#pragma unroll
        for (int h = 0; h < 2; h++) {
            int r = mt * 256 + mw * 64 + m4 * 16 + h * 8 + g;
            float* yb = y + (size_t)r * DIM + nt * 128;
#pragma unroll
            for (int n2 = 0; n2 < 8; n2++) {
                int col = nw * 64 + n2 * 8 + t2;
                float2 v = make_float2(c[m4][n2][2 * h]     + sBias[col],
                                       c[m4][n2][2 * h + 1] + sBias[col + 1]);
                *(float2*)(yb + col) = v;
            }
        }
    }
}

// --------------------------------------------------------------------------
extern "C" void kernel_launch(void* const* d_in, const int* in_sizes, int n_in,
                              void* d_out, int out_size) {
    (void)in_sizes; (void)n_in; (void)out_size;
    const float* x      = (const float*)d_in[0];
    const float* a_log  = (const float*)d_in[1];
    const float* U      = (const float*)d_in[2];
    const float* V      = (const float*)d_in[3];
    const float* Win    = (const float*)d_in[4];
    const float* bin    = (const float*)d_in[5];
    const float* Wgate  = (const float*)d_in[6];
    const float* bgate  = (const float*)d_in[7];
    const float* Wout   = (const float*)d_in[8];
    const float* bout   = (const float*)d_in[9];
    const float* Wskip  = (const float*)d_in[10];
    const float* bskip  = (const float*)d_in[11];
    float* y = (float*)d_out;

    cudaFuncSetAttribute(k_gemm1, cudaFuncAttributeMaxDynamicSharedMemorySize, G1TOTAL);
    cudaFuncSetAttribute(k_gemm2, cudaFuncAttributeMaxDynamicSharedMemorySize, G2TOTAL);

    k_gemm1<<<G1_GEMM_BLKS + G1_PREP_BLKS, 256, G1TOTAL>>>(
        x, Win, Wgate, bin, bgate, a_log, U, V, Wskip, Wout);
    k_scan_local<<<NTASK / 4, 64>>>();
    k_scan_mid<<<BATCH, 512>>>();
    k_fixup<<<ROWS * NST / 4 / 256, 256>>>();
    k_gemm2<<<dim3(6, 128), 256, G2TOTAL>>>(bout, bskip, y);
}

// round 13
// speedup vs baseline: 1.1485x; 1.1485x over previous
#include <cuda_runtime.h>
#include <cuda_fp16.h>
#include <cstdint>
#include <cmath>

constexpr int BATCH = 8;
constexpr int SEQ   = 4096;
constexpr int DIM   = 768;
constexpr int NST   = 16;
constexpr int ROWS  = BATCH * SEQ;        // 32768
constexpr int CHUNK = 128;                // one gemm1 CTA = one chunk
constexpr int NCHUNK = SEQ / CHUNK;       // 32
constexpr int NTASK  = BATCH * NCHUNK;    // 256

__device__ float  d_gu[ROWS * NST];            // scanned local h (written by gemm1)
__device__ float  d_lend[NTASK * NST];
__device__ float  d_hstart[NTASK * NST];
__device__ float  d_Ppow[CHUNK * NST * NST];   // Ppow[j] = T^(j+1), j=0..127 (128 KB)
__device__ float  d_Qsq[5 * NST * NST];        // Qsq[t] = (T^128)^(2^t)
__device__ __half d_xh[ROWS * DIM];            // fp16 x (written by gemm1)
__device__ __half d_wsk[DIM * DIM];            // fp16 W_skip
__device__ __half d_hsh[ROWS * NST];           // fp16 hs (written by fixup)
__device__ __half d_woh[DIM * NST];            // fp16 W_out

#define DEVI __device__ __forceinline__

DEVI uint32_t smem_u32(const void* p) {
    uint32_t a;
    asm("{ .reg .u64 t; cvta.to.shared.u64 t, %1; cvt.u32.u64 %0, t; }" : "=r"(a) : "l"(p));
    return a;
}
DEVI void cpa16(uint32_t dst, const void* src) {
    asm volatile("cp.async.ca.shared.global [%0], [%1], 16;" :: "r"(dst), "l"(src));
}
DEVI void cpa_commit() { asm volatile("cp.async.commit_group;"); }
DEVI void cpa_wait2()  { asm volatile("cp.async.wait_group 2;"); }
DEVI void ldm4(uint32_t* r, uint32_t a) {
    asm volatile("ldmatrix.sync.aligned.m8n8.x4.shared.b16 {%0,%1,%2,%3}, [%4];"
                 : "=r"(r[0]), "=r"(r[1]), "=r"(r[2]), "=r"(r[3]) : "r"(a));
}
DEVI void mma16816(float* c, const uint32_t* a, uint32_t b0, uint32_t b1) {
    asm volatile(
        "mma.sync.aligned.m16n8k16.row.col.f32.f16.f16.f32 "
        "{%0,%1,%2,%3},{%4,%5,%6,%7},{%8,%9},{%0,%1,%2,%3};"
        : "+f"(c[0]), "+f"(c[1]), "+f"(c[2]), "+f"(c[3])
        : "r"(a[0]), "r"(a[1]), "r"(a[2]), "r"(a[3]), "r"(b0), "r"(b1));
}
DEVI float dot4(float4 a, float4 b) {
    return a.x * b.x + a.y * b.y + a.z * b.z + a.w * b.w;
}

// --------------------------------------------------------------------------
// mid scan: Kogge-Stone over 32 chunk states per batch (5 stages)
// --------------------------------------------------------------------------
__global__ void __launch_bounds__(128) k_scan_mid() {
    __shared__ float4 buf0[128], buf1[128];       // 32 chunks x 16 floats
    __shared__ float  Qs[5 * 256];
    int b = blockIdx.x, tid = threadIdx.x;
    for (int i = tid; i < 5 * 256; i += 128) Qs[i] = d_Qsq[i];
    buf0[tid] = ((const float4*)(d_lend + b * NCHUNK * NST))[tid];
    __syncthreads();
    float4* src = buf0;
    float4* dst = buf1;
    int k = tid >> 2, q = tid & 3;
#pragma unroll
    for (int t = 0; t < 5; t++) {
        int o = 1 << t;
        const float4* Q4 = (const float4*)(Qs + t * 256);
        float4 v = src[tid];
        if (k >= o) {
            const float4* sp = src + ((k - o) << 2);
            float4 s0 = sp[0], s1 = sp[1], s2 = sp[2], s3 = sp[3];
            float acc[4];
#pragma unroll
            for (int e = 0; e < 4; e++) {
                int n = q * 4 + e;
                acc[e] = dot4(Q4[n * 4], s0) + dot4(Q4[n * 4 + 1], s1)
                       + dot4(Q4[n * 4 + 2], s2) + dot4(Q4[n * 4 + 3], s3);
            }
            v.x += acc[0]; v.y += acc[1]; v.z += acc[2]; v.w += acc[3];
        }
        dst[tid] = v;
        __syncthreads();
        float4* tmp = src; src = dst; dst = tmp;
    }
    float4 out = (k == 0) ? make_float4(0.f, 0.f, 0.f, 0.f) : src[((k - 1) << 2) + q];
    ((float4*)(d_hstart + (size_t)b * NCHUNK * NST))[tid] = out;
}

// --------------------------------------------------------------------------
// fix-up h_t = local_t + T^(j+1) s_k -> fp16 hs ; float4-vectorized
// --------------------------------------------------------------------------
__global__ void __launch_bounds__(256) k_fixup() {
    int gid = blockIdx.x * 256 + threadIdx.x;
    int r = gid >> 2, q = gid & 3;
    int b = r >> 12, t = r & 4095;
    int k = t >> 7, j = t & 127;
    const float4* P4 = (const float4*)(d_Ppow + j * 256);
    const float4* s4 = (const float4*)(d_hstart + (size_t)(b * NCHUNK + k) * NST);
    float4 s0 = s4[0], s1 = s4[1], s2 = s4[2], s3 = s4[3];
    float4 g = ((const float4*)d_gu)[gid];
    float acc[4] = {g.x, g.y, g.z, g.w};
#pragma unroll
    for (int e = 0; e < 4; e++) {
        int n = q * 4 + e;
        acc[e] += dot4(P4[n * 4], s0) + dot4(P4[n * 4 + 1], s1)
                + dot4(P4[n * 4 + 2], s2) + dot4(P4[n * 4 + 3], s3);
    }
    __half2 h0 = __floats2half2_rn(acc[0], acc[1]);
    __half2 h1 = __floats2half2_rn(acc[2], acc[3]);
    uint2 pk = make_uint2(*(uint32_t*)&h0, *(uint32_t*)&h1);
    ((uint2*)d_hsh)[gid] = pk;
}

// --------------------------------------------------------------------------
// GEMM1 (+ fused prep + in-CTA local scan):
//  blocks 0..255   : gu tile (128 rows = one chunk) + local scan epilogue
//  blocks 256..    : prep (powers/squarings, Wskip->fp16, Wout->fp16)
// --------------------------------------------------------------------------
constexpr int G1_BS = 776;
constexpr int G1_B  = 0;                       // 32*776*2 = 49664
constexpr int G1_A  = 49664;                   // 4 * 128*40*2 = 40960 (reused as sGu)
constexpr int G1_BIAS = G1_A + 40960;          // 90624
constexpr int G1TOTAL = G1_BIAS + 128;
constexpr int AST = 40;
constexpr int G1_GEMM_BLKS = 256;
constexpr int G1_PREP_BLKS = 589;              // 1 powers + 576 Wskip + 12 Wout

__global__ void __launch_bounds__(256, 2) k_gemm1(const float* __restrict__ x,
                                                  const float* __restrict__ Win,
                                                  const float* __restrict__ Wgate,
                                                  const float* __restrict__ bin,
                                                  const float* __restrict__ bgate,
                                                  const float* __restrict__ a_logit,
                                                  const float* __restrict__ U,
                                                  const float* __restrict__ V,
                                                  const float* __restrict__ Wskip,
                                                  const float* __restrict__ Wout) {
    int tid = threadIdx.x;
    if (blockIdx.x >= G1_GEMM_BLKS) {
        int pbid = blockIdx.x - G1_GEMM_BLKS;
        if (pbid == 0) {
            __shared__ float Ts[256], cur[256];
            int n = tid >> 4, m = tid & 15;
            float acc = 0.f;
#pragma unroll
            for (int r = 0; r < 8; r++) acc += V[m * 8 + r] * U[n * 8 + r];
            if (m == n) acc += 1.f / (1.f + expf(-a_logit[n]));
            Ts[tid] = acc; cur[tid] = acc; d_Ppow[tid] = acc;
            __syncthreads();
            for (int j = 1; j < CHUNK; j++) {
                float s = 0.f;
#pragma unroll
                for (int q = 0; q < 16; q++) s += Ts[n * 16 + q] * cur[q * 16 + m];
                __syncthreads();
                cur[tid] = s; d_Ppow[j * 256 + tid] = s;
                __syncthreads();
            }
            // cur = T^128; squarings for mid scan
            for (int tt = 0; tt < 5; tt++) {
                d_Qsq[tt * 256 + tid] = cur[tid];
                float s = 0.f;
#pragma unroll
                for (int q = 0; q < 16; q++) s += cur[n * 16 + q] * cur[q * 16 + m];
                __syncthreads();
                cur[tid] = s;
                __syncthreads();
            }
        } else if (pbid <= 576) {
            int i = (pbid - 1) * 256 + tid;        // float4 index into Wskip
            float4 v = ((const float4*)Wskip)[i];
            ((__half2*)d_wsk)[2 * i]     = __floats2half2_rn(v.x, v.y);
            ((__half2*)d_wsk)[2 * i + 1] = __floats2half2_rn(v.z, v.w);
        } else {
            int j = (pbid - 577) * 256 + tid;      // float4 index into Wout
            if (j < DIM * NST / 4) {
                float4 v = ((const float4*)Wout)[j];
                ((__half2*)d_woh)[2 * j]     = __floats2half2_rn(v.x, v.y);
                ((__half2*)d_woh)[2 * j + 1] = __floats2half2_rn(v.z, v.w);
            }
        }
        return;
    }

    extern __shared__ char smem[];
    __half* sBh = (__half*)(smem + G1_B);
    __half* sAh = (__half*)(smem + G1_A);
    float*  sb  = (float*)(smem + G1_BIAS);
    int w = tid >> 5, l = tid & 31;
    int mt = blockIdx.x;

    for (int i = tid; i < 6144; i += 256) {
        int row = i / 192, c4 = i % 192;
        const float* src = (row < 16) ? (Win + (size_t)row * DIM) : (Wgate + (size_t)(row - 16) * DIM);
        float4 v = ((const float4*)src)[c4];
        *(__half2*)(sBh + row * G1_BS + c4 * 4)     = __floats2half2_rn(v.x, v.y);
        *(__half2*)(sBh + row * G1_BS + c4 * 4 + 2) = __floats2half2_rn(v.z, v.w);
    }
    if (tid < 16) { sb[tid] = bin[tid]; sb[16 + tid] = bgate[tid]; }

    int arow = tid >> 1, ahalf = tid & 1;
    const float* Abase = x + (size_t)(mt * 128 + arow) * DIM + ahalf * 16;
    __half* xdst = d_xh + (size_t)(mt * 128 + arow) * DIM + ahalf * 16;

    auto convert_store = [&](const float4* rg, int kc) {
        uint32_t hp[8];
#pragma unroll
        for (int q = 0; q < 4; q++) {
            __half2 h0 = __floats2half2_rn(rg[q].x, rg[q].y);
            __half2 h1 = __floats2half2_rn(rg[q].z, rg[q].w);
            hp[2 * q]     = *(uint32_t*)&h0;
            hp[2 * q + 1] = *(uint32_t*)&h1;
        }
        __half* Ad = sAh + (kc & 3) * (128 * AST) + arow * AST + ahalf * 16;
        *(uint4*)Ad       = make_uint4(hp[0], hp[1], hp[2], hp[3]);
        *(uint4*)(Ad + 8) = make_uint4(hp[4], hp[5], hp[6], hp[7]);
        *(uint4*)(xdst + kc * 32)     = make_uint4(hp[0], hp[1], hp[2], hp[3]);
        *(uint4*)(xdst + kc * 32 + 8) = make_uint4(hp[4], hp[5], hp[6], hp[7]);
    };

    float4 rg[4];
#pragma unroll
    for (int q = 0; q < 4; q++) rg[q] = ((const float4*)Abase)[q];
    convert_store(rg, 0);
#pragma unroll
    for (int q = 0; q < 4; q++) rg[q] = ((const float4*)(Abase + 32))[q];

    float c[4][4];
#pragma unroll
    for (int i = 0; i < 4; i++)
#pragma unroll
        for (int j = 0; j < 4; j++) c[i][j] = 0.f;

    uint32_t aAddr = smem_u32(sAh);
    uint32_t bAddr = smem_u32(sBh);

    for (int kc = 0; kc < 24; kc++) {
        __syncthreads();
        if (kc < 23) {
            convert_store(rg, kc + 1);
            if (kc < 22) {
                const float4* nsrc = (const float4*)(Abase + (kc + 2) * 32);
#pragma unroll
                for (int q = 0; q < 4; q++) rg[q] = nsrc[q];
            }
        }
        uint32_t Ab = aAddr + (kc & 3) * (128 * AST * 2);
        uint32_t Bb = bAddr + kc * 32 * 2;
#pragma unroll
        for (int ks = 0; ks < 2; ks++) {
            uint32_t a[4];
            ldm4(a, Ab + ((w * 16 + (l & 15)) * AST + ks * 16 + (l >> 4) * 8) * 2);
            uint32_t bf[2][4];
#pragma unroll
            for (int i = 0; i < 2; i++)
                ldm4(bf[i], Bb + ((i * 16 + (l & 15)) * G1_BS + ks * 16 + (l >> 4) * 8) * 2);
#pragma unroll
            for (int nt = 0; nt < 4; nt++)
                mma16816(c[nt], a, bf[nt >> 1][nt & 1], bf[nt >> 1][(nt & 1) + 2]);
        }
    }

    // ---- epilogue: gu -> smem, then in-CTA local scan (chunk = this CTA) ----
    __syncthreads();                       // mma reads of sAh complete
    float* sGu = (float*)(smem + G1_A);    // 128 x 16 f32 = 8 KB (aliases A stages)

    int g = l >> 2, t2 = (l & 3) * 2;
#pragma unroll
    for (int h = 0; h < 2; h++) {
        int rloc = w * 16 + h * 8 + g;
#pragma unroll
        for (int nt = 0; nt < 4; nt += 2) {  // nt in {0,2} pairs with gate (nt+2)
            // only nt<2 are value outputs; handled below
        }
#pragma unroll
        for (int nt = 0; nt < 2; nt++) {
            float v[2];
#pragma unroll
            for (int e = 0; e < 2; e++) {
                int col = nt * 8 + t2 + e;
                float u  = c[nt][2 * h + e] + sb[col];
                float gp = c[nt + 2][2 * h + e] + sb[16 + col];
                v[e] = u / (1.f + expf(-gp));
            }
            *(float2*)(sGu + rloc * 16 + nt * 8 + t2) = make_float2(v[0], v[1]);
        }
    }
    __syncthreads();

    if (w == 0) {
        int n = l & 15;
        // Trow = row n of T
        float un[8];
#pragma unroll
        for (int r = 0; r < 8; r++) un[r] = U[n * 8 + r];
        float sig = 1.f / (1.f + expf(-a_logit[n]));
        float Trow[16];
#pragma unroll
        for (int m = 0; m < 16; m++) {
            float s = 0.f;
#pragma unroll
            for (int r = 0; r < 8; r++) s += V[m * 8 + r] * un[r];
            if (m == n) s += sig;
            Trow[m] = s;
        }
        float h = 0.f;
        for (int j = 0; j < CHUNK; j++) {
            float hn = sGu[j * 16 + n];
#pragma unroll
            for (int m = 0; m < 16; m++)
                hn += Trow[m] * __shfl_sync(0xffffffffu, h, m, 16);
            h = hn;
            sGu[j * 16 + n] = h;
        }
        d_lend[mt * NST + n] = h;          // lanes 16-31 duplicate harmlessly
    }
    __syncthreads();

    float4* gdst = (float4*)(d_gu + (size_t)mt * 128 * NST);
    const float4* gsrc = (const float4*)sGu;
#pragma unroll
    for (int i = 0; i < 2; i++) gdst[tid + i * 256] = gsrc[tid + i * 256];
}

// --------------------------------------------------------------------------
// GEMM2: y = [x | hs] [Wskip | Wout]^T + b_out + b_skip
// 256 threads, 8 warps (4m x 2n), warp tile 32x64; 4-stage cp.async.
// --------------------------------------------------------------------------
constexpr int G2_STG = 20480;
constexpr int G2_BI  = 4 * G2_STG;
constexpr int G2TOTAL = G2_BI + 512;
constexpr int NKT = 25;

__global__ void __launch_bounds__(256, 2) k_gemm2(const float* __restrict__ bout,
                                                  const float* __restrict__ bskip,
                                                  float* __restrict__ y) {
    extern __shared__ char smem[];
    uint32_t sb = smem_u32(smem);
    int tid = threadIdx.x, w = tid >> 5, l = tid & 31;
    int nt = blockIdx.x, mt = blockIdx.y;
    int mw = w >> 1, nw = w & 1;

    float* sBias = (float*)(smem + G2_BI);
    if (tid < 128) sBias[tid] = bout[nt * 128 + tid] + bskip[nt * 128 + tid];

    const __half* Asrc = d_xh + (size_t)mt * 128 * DIM;
    const __half* Bsrc = d_wsk + (size_t)nt * 128 * DIM;
    const __half* Ahs  = d_hsh + (size_t)mt * 128 * NST;
    const __half* Bwo  = d_woh + (size_t)nt * 128 * NST;

    auto load_stage = [&](int kc) {
        uint32_t Ad = sb + (kc & 3) * G2_STG;
        uint32_t Bd = Ad + 10240;
        if (kc < 24) {
#pragma unroll
            for (int q = 0; q < 2; q++) {
                int s = tid + q * 256;
                int row = s >> 2, cs = s & 3;
                cpa16(Ad + (row * AST + cs * 8) * 2, Asrc + (size_t)row * DIM + kc * 32 + cs * 8);
                cpa16(Bd + (row * AST + cs * 8) * 2, Bsrc + (size_t)row * DIM + kc * 32 + cs * 8);
            }
        } else {
#pragma unroll
            for (int q = 0; q < 2; q++) {
                int s = tid + q * 256;
                int row = s >> 2, cs = s & 3;
                if (cs < 2) {
                    cpa16(Ad + (row * AST + cs * 8) * 2, Ahs + row * NST + cs * 8);
                    cpa16(Bd + (row * AST + cs * 8) * 2, Bwo + row * NST + cs * 8);
                } else {
                    *(uint4*)(smem + (kc & 3) * G2_STG + (row * AST + cs * 8) * 2) =
                        make_uint4(0u, 0u, 0u, 0u);
                    *(uint4*)(smem + (kc & 3) * G2_STG + 10240 + (row * AST + cs * 8) * 2) =
                        make_uint4(0u, 0u, 0u, 0u);
                }
            }
        }
    };

    float c[2][8][4];
#pragma unroll
    for (int i = 0; i < 2; i++)
#pragma unroll
        for (int j = 0; j < 8; j++)
#pragma unroll
            for (int e = 0; e < 4; e++) c[i][j][e] = 0.f;

    load_stage(0); cpa_commit();
    load_stage(1); cpa_commit();

    for (int kc = 0; kc < NKT; kc++) {
        if (kc + 2 < NKT) load_stage(kc + 2);
        cpa_commit();
        cpa_wait2();
        __syncthreads();
        uint32_t Ab = sb + (kc & 3) * G2_STG;
        uint32_t Bb = Ab + 10240;
#pragma unroll
        for (int ks = 0; ks < 2; ks++) {
            uint32_t a[2][4];
#pragma unroll
            for (int m2 = 0; m2 < 2; m2++)
                ldm4(a[m2], Ab + ((mw * 32 + m2 * 16 + (l & 15)) * AST + ks * 16 + (l >> 4) * 8) * 2);
            uint32_t bf[4][4];
#pragma unroll
            for (int i = 0; i < 4; i++)
                ldm4(bf[i], Bb + ((nw * 64 + i * 16 + (l & 15)) * AST + ks * 16 + (l >> 4) * 8) * 2);
#pragma unroll
            for (int m2 = 0; m2 < 2; m2++)
#pragma unroll
                for (int n2 = 0; n2 < 8; n2++)
                    mma16816(c[m2][n2], a[m2], bf[n2 >> 1][n2 & 1], bf[n2 >> 1][(n2 & 1) + 2]);
        }
    }

    int g = l >> 2, t2 = (l & 3) * 2;
#pragma unroll
    for (int m2 = 0; m2 < 2; m2++) {
#pragma unroll
        for (int h = 0; h < 2; h++) {
            int r = mt * 128 + mw * 32 + m2 * 16 + h * 8 + g;
            float* yb = y + (size_t)r * DIM + nt * 128;
#pragma unroll
            for (int n2 = 0; n2 < 8; n2++) {
                int col = nw * 64 + n2 * 8 + t2;
                float2 v = make_float2(c[m2][n2][2 * h]     + sBias[col],
                                       c[m2][n2][2 * h + 1] + sBias[col + 1]);
                *(float2*)(yb + col) = v;
            }
        }
    }
}

// --------------------------------------------------------------------------
extern "C" void kernel_launch(void* const* d_in, const int* in_sizes, int n_in,
                              void* d_out, int out_size) {
    (void)in_sizes; (void)n_in; (void)out_size;
    const float* x      = (const float*)d_in[0];
    const float* a_log  = (const float*)d_in[1];
    const float* U      = (const float*)d_in[2];
    const float* V      = (const float*)d_in[3];
    const float* Win    = (const float*)d_in[4];
    const float* bin    = (const float*)d_in[5];
    const float* Wgate  = (const float*)d_in[6];
    const float* bgate  = (const float*)d_in[7];
    const float* Wout   = (const float*)d_in[8];
    const float* bout   = (const float*)d_in[9];
    const float* Wskip  = (const float*)d_in[10];
    const float* bskip  = (const float*)d_in[11];
    float* y = (float*)d_out;

    cudaFuncSetAttribute(k_gemm1, cudaFuncAttributeMaxDynamicSharedMemorySize, G1TOTAL);
    cudaFuncSetAttribute(k_gemm2, cudaFuncAttributeMaxDynamicSharedMemorySize, G2TOTAL);

    k_gemm1<<<G1_GEMM_BLKS + G1_PREP_BLKS, 256, G1TOTAL>>>(
        x, Win, Wgate, bin, bgate, a_log, U, V, Wskip, Wout);
    k_scan_mid<<<BATCH, 128>>>();
    k_fixup<<<ROWS * NST / 4 / 256, 256>>>();
    k_gemm2<<<dim3(6, 256), 256, G2TOTAL>>>(bout, bskip, y);
}